// round 16
// baseline (speedup 1.0000x reference)
#include <cuda_runtime.h>

// WarpImage FINAL — converged optimum, reproduced at 127.4-128.6us ncu /
// 130.0-131.2us bench across 5 independent runs.
//
// Bilinear warp: image [32,1024,2048] f32 + flow [2,1024,2048] f32
//   -> out [32,1024,2048] f32, border value 0.
//
// Structure: one thread per pixel, scalar 4-tap direct gather, 32-channel
// loop (weights/addresses computed once, reused 32x). 32x16 pixel tiles,
// 512 threads, 32 regs, 4 CTAs/SM, channel unroll 4 (16 loads in flight =
// exact register-budget fit).
//
// Closed design space (bench us): this=130.0 | 8-row tile=132 | 32-row=133.9 |
// unroll8=193 | f32x2 merge=159 | f32x4 merge=244 | smem staging=260 |
// 4px/thread=150 | cache hints=neutral | texture gather=forbidden alloc |
// tex bilinear=fails 1e-3 | fp16 two-pass=priced ~140 | px-pair v2 stores,
// warp-shape remap, shuffle tap-sharing = priced neutral-or-worse under the
// measured cost model.
//
// Hardware invariants (measured): divergent-gather L1 cost ~ bytes/lane
// (scalar LDG.32 optimal, 16B/lane-ch floor); l1tex util ceiling ~84%;
// floor = 110us work / 0.84 ~ 128us = achieved. DRAM at compulsory traffic
// (~530MB, 50% of peak BW) — zero redundant DRAM traffic.
//
// Border semantics (exact reference match, rel_err 4.5e-8): independently
// clamped taps via clamp(x+1) = clamp(x) + d; out-of-image taps zeroed
// through their weights.

#define CC 32
#define HH 1024
#define WW 2048
#define HWSZ (HH * WW)

__global__ __launch_bounds__(512, 4) void warp_image_kernel(
    const float* __restrict__ image,
    const float* __restrict__ flow,
    float* __restrict__ out)
{
    const int w = blockIdx.x * 32 + threadIdx.x;
    const int h = blockIdx.y * 16 + threadIdx.y;
    const int idx = h * WW + w;

    float u = (float)w + __ldg(flow + idx);
    float v = (float)h + __ldg(flow + HWSZ + idx);

    float u0f = floorf(u);
    float v0f = floorf(v);
    float wu = u - u0f;
    float wv = v - v0f;

    int u0 = (int)u0f;
    int v0 = (int)v0f;

    bool vu0 = (u0 >= 0) && (u0 <= WW - 1);
    bool vu1 = (u0 + 1 >= 0) && (u0 + 1 <= WW - 1);
    bool vv0 = (v0 >= 0) && (v0 <= HH - 1);
    bool vv1 = (v0 + 1 >= 0) && (v0 + 1 <= HH - 1);

    float w00 = (1.0f - wu) * (1.0f - wv); if (!(vu0 && vv0)) w00 = 0.0f;
    float w10 = wu * (1.0f - wv);          if (!(vu1 && vv0)) w10 = 0.0f;
    float w01 = (1.0f - wu) * wv;          if (!(vu0 && vv1)) w01 = 0.0f;
    float w11 = wu * wv;                   if (!(vu1 && vv1)) w11 = 0.0f;

    int u0c = min(max(u0, 0), WW - 1);
    int v0c = min(max(v0, 0), HH - 1);

    // compact tap addressing: clamp(x+1) = clamp(x) + d
    const int du  = ((u0 >= 0) && (u0 <= WW - 2)) ? 1 : 0;
    const int dvW = ((v0 >= 0) && (v0 <= HH - 2)) ? WW : 0;

    const float* g = image + (v0c * WW + u0c);   // tap (v0,u0), channel 0
    float* o = out + idx;

    #pragma unroll 4
    for (int c = 0; c < CC; c++) {
        float t00 = __ldg(g);
        float t10 = __ldg(g + du);
        float t01 = __ldg(g + dvW);
        float t11 = __ldg(g + dvW + du);
        *o = w00 * t00 + w10 * t10 + w01 * t01 + w11 * t11;
        g += HWSZ;
        o += HWSZ;
    }
}

extern "C" void kernel_launch(void* const* d_in, const int* in_sizes, int n_in,
                              void* d_out, int out_size)
{
    const float* image = (const float*)d_in[0];
    const float* flow  = (const float*)d_in[1];
    float* out = (float*)d_out;

    cudaFuncSetAttribute(warp_image_kernel,
                         cudaFuncAttributePreferredSharedMemoryCarveout, 0);

    dim3 block(32, 16);
    dim3 grid(WW / 32, HH / 16);   // (64, 64)
    warp_image_kernel<<<grid, block>>>(image, flow, out);
}

// round 17
// speedup vs baseline: 1.0284x; 1.0284x over previous
#include <cuda_runtime.h>

// WarpImage FINAL — converged optimum, reproduced across 6 independent runs
// (bench 130.0-133.2us, ncu 127.4-131.3us; identical code, spread = noise).
//
// Bilinear warp: image [32,1024,2048] f32 + flow [2,1024,2048] f32
//   -> out [32,1024,2048] f32, border value 0.
//
// Structure: one thread per pixel, scalar 4-tap direct gather, 32-channel
// loop (weights/addresses computed once, reused 32x). 32x16 pixel tiles,
// 512 threads, 32 regs, 4 CTAs/SM, channel unroll 4 (16 loads in flight =
// exact register-budget fit).
//
// Closed design space (bench us): this=130.0 | 8-row tile=132 | 32-row=133.9 |
// unroll8=193 | f32x2 merge=159 | f32x4 merge=244 | smem staging=260 |
// 4px/thread=150 | cache hints=neutral | texture gather=forbidden alloc |
// tex bilinear=fails 1e-3 | fp16 two-pass ~140 | 2px/float2-stores, warp-shape
// remap, shuffle tap-sharing = priced neutral-or-worse under the measured
// cost model (same-lane same-line requests in different instructions still
// cost separate l1tex wavefronts).
//
// Hardware invariants (measured): divergent-gather L1 cost ~ bytes/lane
// (scalar LDG.32 optimal, 16B/lane-ch floor); l1tex util ceiling ~84%;
// floor = 110us work / 0.84 ~ 128us = achieved. DRAM at compulsory traffic
// (~530MB, 50% of peak BW) — zero redundant DRAM traffic.
//
// Border semantics (exact reference match, rel_err 4.5e-8): independently
// clamped taps via clamp(x+1) = clamp(x) + d; out-of-image taps zeroed
// through their weights.

#define CC 32
#define HH 1024
#define WW 2048
#define HWSZ (HH * WW)

__global__ __launch_bounds__(512, 4) void warp_image_kernel(
    const float* __restrict__ image,
    const float* __restrict__ flow,
    float* __restrict__ out)
{
    const int w = blockIdx.x * 32 + threadIdx.x;
    const int h = blockIdx.y * 16 + threadIdx.y;
    const int idx = h * WW + w;

    float u = (float)w + __ldg(flow + idx);
    float v = (float)h + __ldg(flow + HWSZ + idx);

    float u0f = floorf(u);
    float v0f = floorf(v);
    float wu = u - u0f;
    float wv = v - v0f;

    int u0 = (int)u0f;
    int v0 = (int)v0f;

    bool vu0 = (u0 >= 0) && (u0 <= WW - 1);
    bool vu1 = (u0 + 1 >= 0) && (u0 + 1 <= WW - 1);
    bool vv0 = (v0 >= 0) && (v0 <= HH - 1);
    bool vv1 = (v0 + 1 >= 0) && (v0 + 1 <= HH - 1);

    float w00 = (1.0f - wu) * (1.0f - wv); if (!(vu0 && vv0)) w00 = 0.0f;
    float w10 = wu * (1.0f - wv);          if (!(vu1 && vv0)) w10 = 0.0f;
    float w01 = (1.0f - wu) * wv;          if (!(vu0 && vv1)) w01 = 0.0f;
    float w11 = wu * wv;                   if (!(vu1 && vv1)) w11 = 0.0f;

    int u0c = min(max(u0, 0), WW - 1);
    int v0c = min(max(v0, 0), HH - 1);

    // compact tap addressing: clamp(x+1) = clamp(x) + d
    const int du  = ((u0 >= 0) && (u0 <= WW - 2)) ? 1 : 0;
    const int dvW = ((v0 >= 0) && (v0 <= HH - 2)) ? WW : 0;

    const float* g = image + (v0c * WW + u0c);   // tap (v0,u0), channel 0
    float* o = out + idx;

    #pragma unroll 4
    for (int c = 0; c < CC; c++) {
        float t00 = __ldg(g);
        float t10 = __ldg(g + du);
        float t01 = __ldg(g + dvW);
        float t11 = __ldg(g + dvW + du);
        *o = w00 * t00 + w10 * t10 + w01 * t01 + w11 * t11;
        g += HWSZ;
        o += HWSZ;
    }
}

extern "C" void kernel_launch(void* const* d_in, const int* in_sizes, int n_in,
                              void* d_out, int out_size)
{
    const float* image = (const float*)d_in[0];
    const float* flow  = (const float*)d_in[1];
    float* out = (float*)d_out;

    cudaFuncSetAttribute(warp_image_kernel,
                         cudaFuncAttributePreferredSharedMemoryCarveout, 0);

    dim3 block(32, 16);
    dim3 grid(WW / 32, HH / 16);   // (64, 64)
    warp_image_kernel<<<grid, block>>>(image, flow, out);
}